// round 6
// baseline (speedup 1.0000x reference)
#include <cuda_runtime.h>
#include <cstdint>

#define NT   128          // threads per CTA; 2 threads per problem
#define NPB  64           // problems per CTA
#define SMS  65           // stride over p: bank = (e + p) % 32 -> conflict-free fill & compute

#define MM(r, c) sm[((r) * 13 + (c)) * SMS + p]

// accumulate P[r,I]*w[j] into upper-tri Q (I literal)
#define ACC(I, PV) do { const float p_ = (PV); _Pragma("unroll") \
    for (int j = (I); j < 7; j++) Q[(I)][j] += p_ * w[j]; } while (0)

// one M-row's contribution to Q (R is a literal -> everything constant-folds)
#define SWEEP_ROW(R) do {                                                   \
    float m[13];                                                            \
    _Pragma("unroll")                                                       \
    for (int c = 0; c < 13; c++) m[c] = MM(R, c);                           \
    float w[7];                                                             \
    w[0] = 0.f; w[1] = 0.f; w[2] = 0.f; w[6] = 0.f;                         \
    _Pragma("unroll")                                                       \
    for (int k = 0; k < 3; k++) {                                           \
        w[0] += tc[k]*m[3*k+1] - tb[k]*m[3*k+2];                            \
        w[1] += ta[k]*m[3*k+2] - tc[k]*m[3*k+0];                            \
        w[2] += tb[k]*m[3*k+0] - ta[k]*m[3*k+1];                            \
        w[6] += ta[k]*m[3*k+0] + tb[k]*m[3*k+1] + tc[k]*m[3*k+2];           \
    }                                                                       \
    w[3] = ta[0]*m[10] + ta[1]*m[11] + ta[2]*m[12];                         \
    w[4] = tb[0]*m[10] + tb[1]*m[11] + tb[2]*m[12];                         \
    w[5] = tc[0]*m[10] + tc[1]*m[11] + tc[2]*m[12];                         \
    w[6] += m[9] + td[0]*m[10] + td[1]*m[11] + td[2]*m[12];                 \
    if ((R) < 9) {                                                          \
        const int k_ = (R) / 3, rr_ = (R) - 3 * k_;                         \
        if (rr_ == 0)      { ACC(1, -tc[k_]); ACC(2,  tb[k_]); }            \
        else if (rr_ == 1) { ACC(0,  tc[k_]); ACC(2, -ta[k_]); }            \
        else               { ACC(0, -tb[k_]); ACC(1,  ta[k_]); }            \
    } else {                                                                \
        const int k_ = (R) - 10;                                            \
        ACC(3, ta[k_]); ACC(4, tb[k_]); ACC(5, tc[k_]);                     \
    }                                                                       \
} while (0)

__global__ void __launch_bounds__(NT, 5)
mtm_refine_kernel(const float* __restrict__ Min, const float* __restrict__ Tin,
                  float* __restrict__ outT, float* __restrict__ outOm, int N)
{
    __shared__ float sm[169 * SMS];   // 43,940 B: full M per problem, [elem][problem]
    const int tid   = threadIdx.x;
    const int pbase = blockIdx.x * NPB;

    // ---- cooperative fill: coalesced LDG, conflict-free STS, no divides ----
    {
        int np = N - pbase; if (np > NPB) np = NPB;
        const float* g = Min + (size_t)pbase * 169;
        const int limit = np * 169;
        int p = 0, e = tid;               // tid < 169 so initial p = 0
        for (int idx = tid; idx < limit; idx += NT) {
            sm[e * SMS + p] = g[idx];
            e += NT; if (e >= 169) { e -= 169; p++; }   // NT < 169: one wrap max
        }
    }
    __syncthreads();

    const int p  = tid >> 1;        // problem slot within CTA
    const int h  = tid & 1;         // pair half: row subset
    const int gp = pbase + p;
    if (gp >= N) return;
    const unsigned mask = __activemask();   // pairs exit together -> valid shfl mask

    // ---- load T rows 0..2 (both lanes hold full T) ----
    float ta[3], tb[3], tc[3], td[3];
    {
        const float4* gT = (const float4*)(Tin + (size_t)gp * 16);
        #pragma unroll
        for (int k = 0; k < 3; k++) {
            float4 f = gT[k];
            ta[k] = f.x; tb[k] = f.y; tc[k] = f.z; td[k] = f.w;
        }
    }

    float OmU[6][6];   // upper-tri Omega of last iteration

    #pragma unroll 1   // 5 identical GN iterations
    for (int it = 0; it < 5; ++it) {
        float Q[7][7];
        #pragma unroll
        for (int i = 0; i < 7; i++)
            #pragma unroll
            for (int j = i; j < 7; j++) Q[i][j] = 0.0f;

        // ---- half-sweep: 6 rows per lane (row 9 feeds only unused Q[6][6]) ----
        if (h == 0) {
            SWEEP_ROW(0); SWEEP_ROW(1); SWEEP_ROW(2);
            SWEEP_ROW(3); SWEEP_ROW(4); SWEEP_ROW(5);
        } else {
            SWEEP_ROW(6); SWEEP_ROW(7); SWEEP_ROW(8);
            SWEEP_ROW(10); SWEEP_ROW(11); SWEEP_ROW(12);
        }

        // ---- pair reduction: both lanes end with the identical full Q ----
        #pragma unroll
        for (int i = 0; i < 7; i++)
            #pragma unroll
            for (int j = i; j < 7; j++) {
                if (i == 6) continue;   // Q[6][6] unused
                Q[i][j] += __shfl_xor_sync(mask, Q[i][j], 1);
            }

        // ---- regularization (matches reference) ----
        const float regT = 1e-8f * fmaxf(Q[3][3] + Q[4][4] + Q[5][5], 1.0f);
        #pragma unroll
        for (int i = 0; i < 6; i++) {
            const float dd = (i < 3) ? 10.0f : regT;
            #pragma unroll
            for (int j = i; j < 6; j++)
                OmU[i][j] = Q[i][j] + ((i == j) ? dd : 0.0f);
        }
        float mx = OmU[0][0];
        #pragma unroll
        for (int i = 0; i < 6; i++)
            #pragma unroll
            for (int j = i; j < 6; j++) mx = fmaxf(mx, OmU[i][j]);
        const float reg = 1e-5f * (1.0f + mx);

        float A[6][6];   // upper-tri only
        #pragma unroll
        for (int i = 0; i < 6; i++)
            #pragma unroll
            for (int j = i; j < 6; j++)
                A[i][j] = OmU[i][j] + ((i == j) ? reg : 0.0f);

        // ---- Cholesky solve A v' = q ; v = -v' (duplicated in both lanes) ----
        float L[6][6], di[6];
        #pragma unroll
        for (int j = 0; j < 6; j++) {
            float s = A[j][j];
            #pragma unroll
            for (int k = 0; k < j; k++) s -= L[j][k] * L[j][k];
            di[j] = rsqrtf(s);
            #pragma unroll
            for (int i = j + 1; i < 6; i++) {
                float t = A[j][i];
                #pragma unroll
                for (int k = 0; k < j; k++) t -= L[i][k] * L[j][k];
                L[i][j] = t * di[j];
            }
        }
        float z[6];
        #pragma unroll
        for (int i = 0; i < 6; i++) {
            float s = Q[i][6];              // q[i]
            #pragma unroll
            for (int k = 0; k < i; k++) s -= L[i][k] * z[k];
            z[i] = s * di[i];
        }
        float w6v[6];
        #pragma unroll
        for (int ii = 5; ii >= 0; ii--) {
            float s = z[ii];
            #pragma unroll
            for (int k = ii + 1; k < 6; k++) s -= L[k][ii] * w6v[k];
            w6v[ii] = s * di[ii];
        }

        const float vx = -w6v[0], vy = -w6v[1], vz = -w6v[2];
        const float px = -w6v[3], py = -w6v[4], pz = -w6v[5];

        // ---- closed-form SE(3) exponential ----
        const float th2 = vx*vx + vy*vy + vz*vz;
        float sA, sB, sC;
        if (th2 > 1e-2f) {
            const float th = sqrtf(th2);
            float sn, cn;
            __sincosf(th, &sn, &cn);
            sA = sn / th;
            sB = (1.0f - cn) / th2;
            sC = (1.0f - sA) / th2;
        } else {
            sA = 1.0f - th2 * (1.0f/6.0f)  + th2*th2 * (1.0f/120.0f);
            sB = 0.5f - th2 * (1.0f/24.0f) + th2*th2 * (1.0f/720.0f);
            sC = (1.0f/6.0f) - th2 * (1.0f/120.0f) + th2*th2 * (1.0f/5040.0f);
        }
        const float k00 = -(vy*vy + vz*vz), k11 = -(vx*vx + vz*vz), k22 = -(vx*vx + vy*vy);
        const float kxy = vx*vy, kxz = vx*vz, kyz = vy*vz;

        const float R00 = 1.0f + sB*k00, R01 = -sA*vz + sB*kxy, R02 =  sA*vy + sB*kxz;
        const float R10 =  sA*vz + sB*kxy, R11 = 1.0f + sB*k11, R12 = -sA*vx + sB*kyz;
        const float R20 = -sA*vy + sB*kxz, R21 =  sA*vx + sB*kyz, R22 = 1.0f + sB*k22;

        const float V00 = 1.0f + sC*k00, V01 = -sB*vz + sC*kxy, V02 =  sB*vy + sC*kxz;
        const float V10 =  sB*vz + sC*kxy, V11 = 1.0f + sC*k11, V12 = -sB*vx + sC*kyz;
        const float V20 = -sB*vy + sC*kxz, V21 =  sB*vx + sC*kyz, V22 = 1.0f + sC*k22;

        const float et0 = V00*px + V01*py + V02*pz;
        const float et1 = V10*px + V11*py + V12*pz;
        const float et2 = V20*px + V21*py + V22*pz;

        // ---- T <- T @ expm(hat(v)) (rows 0..2; row 3 unchanged) ----
        #pragma unroll
        for (int k = 0; k < 3; k++) {
            const float r0 = ta[k], r1 = tb[k], r2 = tc[k], r3 = td[k];
            ta[k] = r0*R00 + r1*R10 + r2*R20;
            tb[k] = r0*R01 + r1*R11 + r2*R21;
            tc[k] = r0*R02 + r1*R12 + r2*R22;
            td[k] = r0*et0 + r1*et1 + r2*et2 + r3;
        }
    }

    // ---- outputs (float32); lane 0 writes T, lane 1 writes Omega ----
    if (h == 0) {
        float4* oT = (float4*)(outT + (size_t)gp * 16);
        #pragma unroll
        for (int k = 0; k < 3; k++)
            oT[k] = make_float4(ta[k], tb[k], tc[k], td[k]);
        // last row of T unchanged by boxplus (expm row3 = [0,0,0,1])
        oT[3] = ((const float4*)(Tin + (size_t)gp * 16))[3];
    } else {
        const float tzf = td[2];
        const float sc  = 1.0f / (tzf * tzf + 1e-8f);
        float Of[36];
        #pragma unroll
        for (int i = 0; i < 6; i++)
            #pragma unroll
            for (int j = 0; j < 6; j++)
                Of[i*6 + j] = ((i <= j) ? OmU[i][j] : OmU[j][i]) * sc;
        float4* oO = (float4*)(outOm + (size_t)gp * 36);
        #pragma unroll
        for (int v4 = 0; v4 < 9; v4++)
            oO[v4] = make_float4(Of[v4*4+0], Of[v4*4+1], Of[v4*4+2], Of[v4*4+3]);
    }
}

extern "C" void kernel_launch(void* const* d_in, const int* in_sizes, int n_in,
                              void* d_out, int out_size)
{
    const float* Min = (const float*)d_in[0];   // MTMs [B,C,13,13] fp32
    const float* Tin = (const float*)d_in[1];   // Ts   [B,C,4,4]   fp32
    const int N = in_sizes[0] / 169;

    float* out   = (float*)d_out;
    float* outT  = out;                          // [N,4,4]
    float* outOm = out + (size_t)N * 16;         // [N,6,6]

    const int blocks = (N + NPB - 1) / NPB;
    mtm_refine_kernel<<<blocks, NT>>>(Min, Tin, outT, outOm, N);
}